// round 9
// baseline (speedup 1.0000x reference)
#include <cuda_runtime.h>

// Problem constants
#define NB   16        // batches
#define NPB  262144    // elements per batch (512*512)
#define HB   64        // histogram bins
#define HC   64        // hist CTAs per batch
#define HT   128       // hist threads per CTA
// per hist CTA: NPB/HC = 4096 elements = 1024 float4; per thread 8 float4

#define KL_EPS 1e-8f
#define WEIGHT 0.1f

// ---------------- device scratch (no allocations allowed) ----------------
__device__ unsigned int g_minkey[NB];
__device__ unsigned int g_maxkey[NB];
__device__ float        g_part[NB][HC][2][HB];   // [batch][cta][target=0/pred=1][bin]

// ---------------- float <-> orderable-uint key ----------------
__device__ __forceinline__ unsigned int f2key(float x) {
    unsigned int i = __float_as_uint(x);
    return (i & 0x80000000u) ? ~i : (i | 0x80000000u);
}
__device__ __forceinline__ float key2f(unsigned int k) {
    unsigned int i = (k & 0x80000000u) ? (k ^ 0x80000000u) : ~k;
    return __uint_as_float(i);
}

// ---------------- kernel 0: init min/max keys ----------------
__global__ void k_init() {
    int t = threadIdx.x;
    if (t < NB) { g_minkey[t] = 0xFFFFFFFFu; g_maxkey[t] = 0u; }
}

// ---------------- kernel 1: per-batch min/max of target ----------------
// grid (16, NB), 256 threads. Each CTA handles 4096 float4 = 16384 floats.
__global__ void __launch_bounds__(256) k_minmax(const float* __restrict__ target) {
    const int b = blockIdx.y;
    const float4* base = reinterpret_cast<const float4*>(target)
                         + (size_t)b * (NPB / 4) + (size_t)blockIdx.x * 4096;
    float lo = __int_as_float(0x7f800000);   // +inf
    float hi = __int_as_float(0xff800000);   // -inf
    #pragma unroll 4
    for (int i = threadIdx.x; i < 4096; i += 256) {
        float4 v = base[i];
        lo = fminf(lo, fminf(fminf(v.x, v.y), fminf(v.z, v.w)));
        hi = fmaxf(hi, fmaxf(fmaxf(v.x, v.y), fmaxf(v.z, v.w)));
    }
    #pragma unroll
    for (int o = 16; o; o >>= 1) {
        lo = fminf(lo, __shfl_xor_sync(0xffffffffu, lo, o));
        hi = fmaxf(hi, __shfl_xor_sync(0xffffffffu, hi, o));
    }
    __shared__ float slo[8], shi[8];
    int w = threadIdx.x >> 5;
    if ((threadIdx.x & 31) == 0) { slo[w] = lo; shi[w] = hi; }
    __syncthreads();
    if (threadIdx.x == 0) {
        #pragma unroll
        for (int k = 1; k < 8; k++) { lo = fminf(lo, slo[k]); hi = fmaxf(hi, shi[k]); }
        atomicMin(&g_minkey[b], f2key(lo));
        atomicMax(&g_maxkey[b], f2key(hi));
    }
}

// ---------------- kernel 2: soft histograms ----------------
// Gaussian KDE with sigma = 1 bin. Truncated 17-bin window (|d| <= ~8.5;
// dropped terms <= exp(-28.1) ~ 6e-13 per element).
// Recurrence: g(j+1) = g(j)*t,  t(next) = t*e^-1, so only 2 __expf per element.
// Per-thread SMEM histograms: hist[bin*HT + tid] -> bank-conflict-free, no atomics.
__global__ void __launch_bounds__(HT) k_hist(const float* __restrict__ pred,
                                             const float* __restrict__ target) {
    __shared__ float hist[HB * HT];   // 32 KB
    const int b   = blockIdx.y;
    const int c   = blockIdx.x;
    const int tid = threadIdx.x;

    const float vmin  = key2f(g_minkey[b]);
    const float vmax  = key2f(g_maxkey[b]);
    const float denom = vmax - vmin + KL_EPS;
    const float scale = 64.0f / denom;
    const float EINV  = 0.36787944117144233f;  // e^-1

    #pragma unroll 1
    for (int phase = 0; phase < 2; phase++) {
        const float* src = (phase == 0) ? target : pred;
        const float4* base = reinterpret_cast<const float4*>(src)
                             + (size_t)b * (NPB / 4) + (size_t)c * (NPB / 4 / HC);

        // zero per-thread hist slice
        #pragma unroll
        for (int j = 0; j < HB; j++) hist[j * HT + tid] = 0.0f;
        __syncthreads();

        #pragma unroll 1
        for (int i = tid; i < NPB / 4 / HC; i += HT) {
            float4 v = base[i];
            float xs[4] = {v.x, v.y, v.z, v.w};
            #pragma unroll
            for (int e = 0; e < 4; e++) {
                float u  = (xs[e] - vmin) * scale;     // position in bin units
                float jf = floorf(u);
                int   j0 = (int)jf - 8;
                float d  = (u - jf) + 7.5f;            // d at bin j0: in [7.5, 8.5)
                float g  = __expf(-0.5f * d * d);
                float t  = __expf(d - 0.5f);
                #pragma unroll
                for (int k = 0; k < 17; k++) {
                    int j = j0 + k;
                    if ((unsigned)j < (unsigned)HB)
                        hist[j * HT + tid] += g;
                    g *= t;
                    t *= EINV;
                }
            }
        }
        __syncthreads();

        // reduce 128 per-thread slices -> 64 bins (rotated, conflict-free)
        if (tid < HB) {
            const int bin = tid;
            float s0 = 0.f, s1 = 0.f, s2 = 0.f, s3 = 0.f;
            #pragma unroll 4
            for (int s = 0; s < HT; s += 4) {
                s0 += hist[bin * HT + ((s + 0 + bin) & (HT - 1))];
                s1 += hist[bin * HT + ((s + 1 + bin) & (HT - 1))];
                s2 += hist[bin * HT + ((s + 2 + bin) & (HT - 1))];
                s3 += hist[bin * HT + ((s + 3 + bin) & (HT - 1))];
            }
            g_part[b][c][phase][bin] = (s0 + s1) + (s2 + s3);
        }
        __syncthreads();
    }
}

// ---------------- kernel 3: finalize (deterministic fixed-order sums) ----------------
__global__ void __launch_bounds__(256) k_final(float* __restrict__ out) {
    __shared__ float hsum[NB][2][HB];   // 8 KB
    __shared__ float kls[NB];
    const int tid = threadIdx.x;

    // reduce over CTA partials: 16*2*64 = 2048 tasks
    for (int task = tid; task < NB * 2 * HB; task += 256) {
        int b = task / (2 * HB);
        int r = task % (2 * HB);
        int p = r / HB;
        int j = r % HB;
        float s = 0.0f;
        #pragma unroll 4
        for (int c = 0; c < HC; c++) s += g_part[b][c][p][j];
        hsum[b][p][j] = s;
    }
    __syncthreads();

    if (tid < NB) {
        const int b = tid;
        float st = 0.f, sp = 0.f;
        #pragma unroll
        for (int j = 0; j < HB; j++) { st += hsum[b][0][j]; sp += hsum[b][1][j]; }
        float rt = 1.0f / (st + KL_EPS);
        float rp = 1.0f / (sp + KL_EPS);
        float kl = 0.0f;
        #pragma unroll 1
        for (int j = 0; j < HB; j++) {
            float tp = hsum[b][0][j] * rt;
            float pp = hsum[b][1][j] * rp;
            kl += tp * (logf(tp + KL_EPS) - logf(pp + KL_EPS));
        }
        kls[b] = kl;
    }
    __syncthreads();

    if (tid == 0) {
        float s = 0.0f;
        #pragma unroll
        for (int b = 0; b < NB; b++) s += kls[b];
        out[0] = WEIGHT * (s / (float)NB);
    }
}

// ---------------- launch ----------------
extern "C" void kernel_launch(void* const* d_in, const int* in_sizes, int n_in,
                              void* d_out, int out_size) {
    const float* pred   = (const float*)d_in[0];
    const float* target = (const float*)d_in[1];
    float* out = (float*)d_out;

    k_init  <<<1, 32>>>();
    k_minmax<<<dim3(16, NB), 256>>>(target);
    k_hist  <<<dim3(HC, NB), HT>>>(pred, target);
    k_final <<<1, 256>>>(out);
}

// round 10
// speedup vs baseline: 1.8893x; 1.8893x over previous
#include <cuda_runtime.h>

// Problem constants
#define NB   16        // batches
#define NPB  262144    // elements per batch (512*512)
#define HB   64        // histogram bins
#define HC   64        // hist CTAs per batch
#define HT   128       // hist threads per CTA

#define KL_EPS 1e-8f
#define WEIGHT 0.1f

// ---------------- device scratch (no allocations allowed) ----------------
__device__ unsigned int g_minkey[NB];
__device__ unsigned int g_maxkey[NB];
__device__ float        g_part[NB][HC][2][HB];   // [batch][cta][target=0/pred=1][bin]
__device__ float        g_hsum[NB][2][HB];       // reduced histograms

// ---------------- float <-> orderable-uint key ----------------
__device__ __forceinline__ unsigned int f2key(float x) {
    unsigned int i = __float_as_uint(x);
    return (i & 0x80000000u) ? ~i : (i | 0x80000000u);
}
__device__ __forceinline__ float key2f(unsigned int k) {
    unsigned int i = (k & 0x80000000u) ? (k ^ 0x80000000u) : ~k;
    return __uint_as_float(i);
}

// ---------------- kernel 0: init min/max keys ----------------
__global__ void k_init() {
    int t = threadIdx.x;
    if (t < NB) { g_minkey[t] = 0xFFFFFFFFu; g_maxkey[t] = 0u; }
}

// ---------------- kernel 1: per-batch min/max of target ----------------
__global__ void __launch_bounds__(256) k_minmax(const float* __restrict__ target) {
    const int b = blockIdx.y;
    const float4* base = reinterpret_cast<const float4*>(target)
                         + (size_t)b * (NPB / 4) + (size_t)blockIdx.x * 4096;
    float lo = __int_as_float(0x7f800000);   // +inf
    float hi = __int_as_float(0xff800000);   // -inf
    #pragma unroll 4
    for (int i = threadIdx.x; i < 4096; i += 256) {
        float4 v = base[i];
        lo = fminf(lo, fminf(fminf(v.x, v.y), fminf(v.z, v.w)));
        hi = fmaxf(hi, fmaxf(fmaxf(v.x, v.y), fmaxf(v.z, v.w)));
    }
    #pragma unroll
    for (int o = 16; o; o >>= 1) {
        lo = fminf(lo, __shfl_xor_sync(0xffffffffu, lo, o));
        hi = fmaxf(hi, __shfl_xor_sync(0xffffffffu, hi, o));
    }
    __shared__ float slo[8], shi[8];
    int w = threadIdx.x >> 5;
    if ((threadIdx.x & 31) == 0) { slo[w] = lo; shi[w] = hi; }
    __syncthreads();
    if (threadIdx.x == 0) {
        #pragma unroll
        for (int k = 1; k < 8; k++) { lo = fminf(lo, slo[k]); hi = fmaxf(hi, shi[k]); }
        atomicMin(&g_minkey[b], f2key(lo));
        atomicMax(&g_maxkey[b], f2key(hi));
    }
}

// ---------------- kernel 2: soft histograms ----------------
// Gaussian KDE, sigma = 1 bin, 17-bin truncated window (dropped <= 6e-13/elem).
// CENTER-OUT recurrence: seed at the center bin (max-weight) with precise expf,
// recur outward so rounding accumulates only where g is already tiny.
//   up:   g(m+1) = g(m) * r,  r0 = exp(c - 0.5),  r *= e^-1
//   down: g(m+1) = g(m) * q,  q0 = exp(-c - 0.5), q *= e^-1
// Per-thread SMEM histograms hist[bin*HT + tid] -> conflict-free, no atomics.
__global__ void __launch_bounds__(HT) k_hist(const float* __restrict__ pred,
                                             const float* __restrict__ target) {
    __shared__ float hist[HB * HT];   // 32 KB
    const int b   = blockIdx.y;
    const int c0  = blockIdx.x;
    const int tid = threadIdx.x;

    const float vmin  = key2f(g_minkey[b]);
    const float vmax  = key2f(g_maxkey[b]);
    const float denom = vmax - vmin + KL_EPS;
    const float scale = 64.0f / denom;
    const float EINV  = 0.36787944117144233f;  // e^-1

    #pragma unroll 1
    for (int phase = 0; phase < 2; phase++) {
        const float* src = (phase == 0) ? target : pred;
        const float4* base = reinterpret_cast<const float4*>(src)
                             + (size_t)b * (NPB / 4) + (size_t)c0 * (NPB / 4 / HC);

        #pragma unroll
        for (int j = 0; j < HB; j++) hist[j * HT + tid] = 0.0f;
        __syncthreads();

        #pragma unroll 1
        for (int i = tid; i < NPB / 4 / HC; i += HT) {
            float4 v = base[i];
            float xs[4] = {v.x, v.y, v.z, v.w};
            #pragma unroll
            for (int e = 0; e < 4; e++) {
                float u  = (xs[e] - vmin) * scale;   // position in bin units
                float jf = floorf(u);
                int   jc = (int)jf;                  // center bin (contains u)
                float c  = u - jf - 0.5f;            // dist to center bin's center
                float g0 = expf(-0.5f * c * c);
                float r  = expf(c - 0.5f);           // upward ratio seed
                float q  = expf(-c - 0.5f);          // downward ratio seed

                if ((unsigned)jc < (unsigned)HB) hist[jc * HT + tid] += g0;
                float gu = g0, gd = g0;
                #pragma unroll
                for (int m = 1; m <= 8; m++) {
                    gu *= r;
                    int ju = jc + m;
                    if ((unsigned)ju < (unsigned)HB) hist[ju * HT + tid] += gu;
                    r *= EINV;
                    gd *= q;
                    int jd = jc - m;
                    if ((unsigned)jd < (unsigned)HB) hist[jd * HT + tid] += gd;
                    q *= EINV;
                }
            }
        }
        __syncthreads();

        // reduce 128 per-thread slices -> 64 bins (rotated, conflict-free)
        if (tid < HB) {
            const int bin = tid;
            float s0 = 0.f, s1 = 0.f, s2 = 0.f, s3 = 0.f;
            #pragma unroll 4
            for (int s = 0; s < HT; s += 4) {
                s0 += hist[bin * HT + ((s + 0 + bin) & (HT - 1))];
                s1 += hist[bin * HT + ((s + 1 + bin) & (HT - 1))];
                s2 += hist[bin * HT + ((s + 2 + bin) & (HT - 1))];
                s3 += hist[bin * HT + ((s + 3 + bin) & (HT - 1))];
            }
            g_part[b][c0][phase][bin] = (s0 + s1) + (s2 + s3);
        }
        __syncthreads();
    }
}

// ---------------- kernel 3: parallel reduce of CTA partials ----------------
// 32 CTAs (one per batch x phase), 64 threads (one per bin). Coalesced loads,
// fixed summation order -> deterministic.
__global__ void __launch_bounds__(HB) k_reduce() {
    const int b = blockIdx.x >> 1;
    const int p = blockIdx.x & 1;
    const int j = threadIdx.x;
    float s = 0.0f;
    #pragma unroll 8
    for (int c = 0; c < HC; c++) s += g_part[b][c][p][j];
    g_hsum[b][p][j] = s;
}

// ---------------- kernel 4: KL + final scalar (tiny, parallel) ----------------
__global__ void __launch_bounds__(1024) k_final(float* __restrict__ out) {
    __shared__ float sterm[NB * HB];   // 4 KB
    __shared__ float srt[NB], srp[NB];
    const int tid = threadIdx.x;       // 0..1023
    const int b = tid >> 6;            // batch
    const int j = tid & (HB - 1);      // bin

    const float t = g_hsum[b][0][j];
    const float p = g_hsum[b][1][j];

    // per-batch hist sums: 16 threads, fixed order
    if (tid < NB) {
        float st = 0.f, sp = 0.f;
        #pragma unroll
        for (int k = 0; k < HB; k++) { st += g_hsum[tid][0][k]; sp += g_hsum[tid][1][k]; }
        srt[tid] = 1.0f / (st + KL_EPS);
        srp[tid] = 1.0f / (sp + KL_EPS);
    }
    __syncthreads();

    const float tp = t * srt[b];
    const float pp = p * srp[b];
    sterm[tid] = tp * (logf(tp + KL_EPS) - logf(pp + KL_EPS));
    __syncthreads();

    // deterministic tree reduction over all 1024 (b,j) terms
    #pragma unroll
    for (int s = 512; s > 0; s >>= 1) {
        if (tid < s) sterm[tid] += sterm[tid + s];
        __syncthreads();
    }
    if (tid == 0) out[0] = WEIGHT * (sterm[0] / (float)NB);
}

// ---------------- launch ----------------
extern "C" void kernel_launch(void* const* d_in, const int* in_sizes, int n_in,
                              void* d_out, int out_size) {
    const float* pred   = (const float*)d_in[0];
    const float* target = (const float*)d_in[1];
    float* out = (float*)d_out;

    k_init  <<<1, 32>>>();
    k_minmax<<<dim3(16, NB), 256>>>(target);
    k_hist  <<<dim3(HC, NB), HT>>>(pred, target);
    k_reduce<<<NB * 2, HB>>>();
    k_final <<<1, 1024>>>(out);
}

// round 11
// speedup vs baseline: 2.2591x; 1.1957x over previous
#include <cuda_runtime.h>

// Problem constants
#define NB   16        // batches
#define NPB  262144    // elements per batch (512*512)
#define HB   64        // histogram bins
#define HC   64        // hist CTAs per batch
#define HT   128       // hist threads per CTA
#define MC   16        // minmax CTAs per batch

#define KL_EPS 1e-8f
#define WEIGHT 0.1f

// ---------------- device scratch (no allocations allowed) ----------------
__device__ float g_pmin[NB][MC];
__device__ float g_pmax[NB][MC];
__device__ float g_part[NB][2][HC][HB];   // [batch][target=0/pred=1][cta][bin]
__device__ float g_hsum[NB][2][HB];       // reduced histograms

// ---------------- kernel 1: per-batch min/max partials (no atomics) ----------------
// grid (MC, NB), 256 threads. Each CTA handles 4096 float4 = 16384 floats.
__global__ void __launch_bounds__(256) k_minmax(const float* __restrict__ target) {
    const int b = blockIdx.y;
    const float4* base = reinterpret_cast<const float4*>(target)
                         + (size_t)b * (NPB / 4) + (size_t)blockIdx.x * (NPB / 4 / MC);
    float lo = __int_as_float(0x7f800000);   // +inf
    float hi = __int_as_float(0xff800000);   // -inf
    #pragma unroll 8
    for (int i = threadIdx.x; i < NPB / 4 / MC; i += 256) {
        float4 v = base[i];
        lo = fminf(lo, fminf(fminf(v.x, v.y), fminf(v.z, v.w)));
        hi = fmaxf(hi, fmaxf(fmaxf(v.x, v.y), fmaxf(v.z, v.w)));
    }
    #pragma unroll
    for (int o = 16; o; o >>= 1) {
        lo = fminf(lo, __shfl_xor_sync(0xffffffffu, lo, o));
        hi = fmaxf(hi, __shfl_xor_sync(0xffffffffu, hi, o));
    }
    __shared__ float slo[8], shi[8];
    int w = threadIdx.x >> 5;
    if ((threadIdx.x & 31) == 0) { slo[w] = lo; shi[w] = hi; }
    __syncthreads();
    if (threadIdx.x == 0) {
        #pragma unroll
        for (int k = 1; k < 8; k++) { lo = fminf(lo, slo[k]); hi = fmaxf(hi, shi[k]); }
        g_pmin[b][blockIdx.x] = lo;
        g_pmax[b][blockIdx.x] = hi;
    }
}

// ---------------- kernel 2: soft histograms ----------------
// Gaussian KDE, sigma = 1 bin, 13-bin truncated window (dropped <= 6.8e-10/elem
// -> per-bin relative error ~1e-9, far below the fp32 rounding floor).
// CENTER-OUT recurrence seeded with precise expf at the max-weight center bin:
//   up:   g *= r,  r0 = exp(c - 0.5),  r *= e^-1
//   down: g *= q,  q0 = exp(-c - 0.5), q *= e^-1
// Per-thread SMEM histograms hist[bin*HT + tid] -> bank-conflict-free, no atomics.
__global__ void __launch_bounds__(HT) k_hist(const float* __restrict__ pred,
                                             const float* __restrict__ target) {
    __shared__ float hist[HB * HT];   // 32 KB
    __shared__ float s_vmin, s_scale;
    const int b   = blockIdx.y;
    const int c0  = blockIdx.x;
    const int tid = threadIdx.x;
    const float EINV = 0.36787944117144233f;  // e^-1

    if (tid == 0) {
        float lo = g_pmin[b][0], hi = g_pmax[b][0];
        #pragma unroll
        for (int k = 1; k < MC; k++) {
            lo = fminf(lo, g_pmin[b][k]);
            hi = fmaxf(hi, g_pmax[b][k]);
        }
        s_vmin  = lo;
        s_scale = 64.0f / (hi - lo + KL_EPS);
    }

    #pragma unroll 1
    for (int phase = 0; phase < 2; phase++) {
        const float* src = (phase == 0) ? target : pred;
        const float4* base = reinterpret_cast<const float4*>(src)
                             + (size_t)b * (NPB / 4) + (size_t)c0 * (NPB / 4 / HC);

        #pragma unroll
        for (int j = 0; j < HB; j++) hist[j * HT + tid] = 0.0f;
        __syncthreads();

        const float vmin  = s_vmin;
        const float scale = s_scale;

        #pragma unroll 1
        for (int i = tid; i < NPB / 4 / HC; i += HT) {
            float4 v = base[i];
            float xs[4] = {v.x, v.y, v.z, v.w};
            #pragma unroll
            for (int e = 0; e < 4; e++) {
                float u  = (xs[e] - vmin) * scale;   // position in bin units
                float jf = floorf(u);
                int   jc = (int)jf;                  // center bin (contains u)
                float c  = u - jf - 0.5f;            // offset from center bin's center
                float g0 = expf(-0.5f * c * c);
                float r  = expf(c - 0.5f);           // upward ratio seed
                float q  = expf(-c - 0.5f);          // downward ratio seed

                if ((unsigned)jc < (unsigned)HB) hist[jc * HT + tid] += g0;
                float gu = g0, gd = g0;
                #pragma unroll
                for (int m = 1; m <= 6; m++) {
                    gu *= r;
                    int ju = jc + m;
                    if ((unsigned)ju < (unsigned)HB) hist[ju * HT + tid] += gu;
                    r *= EINV;
                    gd *= q;
                    int jd = jc - m;
                    if ((unsigned)jd < (unsigned)HB) hist[jd * HT + tid] += gd;
                    q *= EINV;
                }
            }
        }
        __syncthreads();

        // reduce 128 per-thread slices -> 64 bins (rotated, conflict-free)
        if (tid < HB) {
            const int bin = tid;
            float s0 = 0.f, s1 = 0.f, s2 = 0.f, s3 = 0.f;
            #pragma unroll 4
            for (int s = 0; s < HT; s += 4) {
                s0 += hist[bin * HT + ((s + 0 + bin) & (HT - 1))];
                s1 += hist[bin * HT + ((s + 1 + bin) & (HT - 1))];
                s2 += hist[bin * HT + ((s + 2 + bin) & (HT - 1))];
                s3 += hist[bin * HT + ((s + 3 + bin) & (HT - 1))];
            }
            g_part[b][phase][c0][bin] = (s0 + s1) + (s2 + s3);
        }
        __syncthreads();
    }
}

// ---------------- kernel 3: parallel reduce of CTA partials ----------------
// 32 CTAs (one per batch x phase), 256 threads. Layout g_part[b][p][c][j] is
// contiguous per (b,p): consecutive tid -> consecutive j -> coalesced loads.
// Each thread sums 16 partials (unrolled -> MLP=16); 4 chunk-partials combined
// in fixed order -> deterministic.
__global__ void __launch_bounds__(256) k_reduce() {
    __shared__ float sp[4][HB];
    const int b  = blockIdx.x >> 1;
    const int p  = blockIdx.x & 1;
    const int j  = threadIdx.x & (HB - 1);
    const int cc = threadIdx.x >> 6;        // chunk 0..3
    float s = 0.0f;
    #pragma unroll
    for (int k = 0; k < HC / 4; k++) s += g_part[b][p][cc * (HC / 4) + k][j];
    sp[cc][j] = s;
    __syncthreads();
    if (threadIdx.x < HB) {
        const int jj = threadIdx.x;
        g_hsum[b][p][jj] = (sp[0][jj] + sp[1][jj]) + (sp[2][jj] + sp[3][jj]);
    }
}

// ---------------- kernel 4: KL + final scalar ----------------
__global__ void __launch_bounds__(1024) k_final(float* __restrict__ out) {
    __shared__ float sterm[NB * HB];   // 4 KB
    __shared__ float srt[NB], srp[NB];
    const int tid = threadIdx.x;       // 0..1023
    const int b = tid >> 6;            // batch
    const int j = tid & (HB - 1);      // bin

    const float t = g_hsum[b][0][j];
    const float p = g_hsum[b][1][j];

    if (tid < NB) {
        float st = 0.f, sp = 0.f;
        #pragma unroll
        for (int k = 0; k < HB; k++) { st += g_hsum[tid][0][k]; sp += g_hsum[tid][1][k]; }
        srt[tid] = 1.0f / (st + KL_EPS);
        srp[tid] = 1.0f / (sp + KL_EPS);
    }
    __syncthreads();

    const float tp = t * srt[b];
    const float pp = p * srp[b];
    sterm[tid] = tp * (logf(tp + KL_EPS) - logf(pp + KL_EPS));
    __syncthreads();

    #pragma unroll
    for (int s = 512; s > 0; s >>= 1) {
        if (tid < s) sterm[tid] += sterm[tid + s];
        __syncthreads();
    }
    if (tid == 0) out[0] = WEIGHT * (sterm[0] / (float)NB);
}

// ---------------- launch ----------------
extern "C" void kernel_launch(void* const* d_in, const int* in_sizes, int n_in,
                              void* d_out, int out_size) {
    const float* pred   = (const float*)d_in[0];
    const float* target = (const float*)d_in[1];
    float* out = (float*)d_out;

    k_minmax<<<dim3(MC, NB), 256>>>(target);
    k_hist  <<<dim3(HC, NB), HT>>>(pred, target);
    k_reduce<<<NB * 2, 256>>>();
    k_final <<<1, 1024>>>(out);
}